// round 14
// baseline (speedup 1.0000x reference)
#include <cuda_runtime.h>
#include <cuda_fp16.h>
#include <math.h>

// Problem dims
#define Nb 64
#define Tt 512
#define Ii 512
#define Hh 1024
#define Oo 512
#define MROWS (Nb*Tt)
#define NH (Nb*Hh)
#define RNN_NCTA 128

typedef unsigned long long ull;

// ---------------- scratch ----------------
__device__ float  g_inp1 [(size_t)Tt * NH];      // inp_v [T][N][H] fp32
__device__ float  g_inp2 [(size_t)Tt * NH];      // inp_m [T][N][H] fp32
__device__ __half g_hs16 [(size_t)Tt * NH];      // h state fp16 [T][N][H]
__device__ float  g_tmp  [(size_t)Tt * Nb * Oo];
__device__ float  g_out_t[(size_t)Tt * Nb * Oo];
__device__ __half g_h016a[NH];
__device__ __half g_h016b[NH];
__device__ unsigned g_l1[16 * 32];
__device__ unsigned g_l2;
__device__ volatile unsigned g_gen[16 * 32];

// ---------------- helpers ----------------
__device__ __forceinline__ ull ffma2(ull a, ull b, ull c) {
    ull d;
    asm("fma.rn.f32x2 %0, %1, %2, %3;" : "=l"(d) : "l"(a), "l"(b), "l"(c));
    return d;
}
__device__ __forceinline__ float2 unpack2(ull v) {
    float2 r;
    asm("mov.b64 {%0, %1}, %2;" : "=f"(r.x), "=f"(r.y) : "l"(v));
    return r;
}
__device__ __forceinline__ ull dup2(float v) {
    ull r;
    asm("mov.b64 %0, {%1, %1};" : "=l"(r) : "f"(v));
    return r;
}
__device__ __forceinline__ float retanh(float x) {
    return x > 0.f ? tanhf(x) : 0.f;
}
__device__ __forceinline__ unsigned smem_u32(const void* p) {
    return (unsigned)__cvta_generic_to_shared(p);
}
__device__ __forceinline__ float4 ld4h(const __half* p) {
    uint2 u = *(const uint2*)p;
    __half2 a = *reinterpret_cast<__half2*>(&u.x);
    __half2 b = *reinterpret_cast<__half2*>(&u.y);
    float2 fa = __half22float2(a), fb = __half22float2(b);
    return make_float4(fa.x, fa.y, fb.x, fb.y);
}
#define CP_ASYNC16(dst, src) \
    asm volatile("cp.async.cg.shared.global [%0], [%1], 16;" :: "r"(dst), "l"(src))
#define CP_COMMIT() asm volatile("cp.async.commit_group;" ::: "memory")
#define CP_WAIT0()  asm volatile("cp.async.wait_group 0;" ::: "memory")
#define LDSM_X4(r0, r1, r2, r3, addr) \
    asm volatile("ldmatrix.sync.aligned.m8n8.x4.shared.b16 {%0,%1,%2,%3}, [%4];" \
        : "=r"(r0), "=r"(r1), "=r"(r2), "=r"(r3) : "r"(addr))
#define LDSM_X2(r0, r1, addr) \
    asm volatile("ldmatrix.sync.aligned.m8n8.x2.shared.b16 {%0,%1}, [%2];" \
        : "=r"(r0), "=r"(r1) : "r"(addr))
#define MMA16816(c0, c1, c2, c3, a0, a1, a2, a3, b0, b1) \
    asm volatile("mma.sync.aligned.m16n8k16.row.col.f32.f16.f16.f32 " \
        "{%0,%1,%2,%3}, {%4,%5,%6,%7}, {%8,%9}, {%0,%1,%2,%3};" \
        : "+f"(c0), "+f"(c1), "+f"(c2), "+f"(c3) \
        : "r"(a0), "r"(a1), "r"(a2), "r"(a3), "r"(b0), "r"(b1))

__global__ void reset_barrier_kernel() {
    int t = threadIdx.x;
    if (t < 16 * 32) { g_l1[t] = 0u; g_gen[t] = 0u; }
    if (t == 0) g_l2 = 0u;
}

// tree arrival + fan-out release (16 gen lines, 8 pollers each)
__device__ __forceinline__ void tree_barrier(int bx, unsigned target) {
    __syncthreads();
    if (threadIdx.x == 0) {
        __threadfence();
        unsigned o1 = atomicAdd(&g_l1[(bx >> 3) * 32], 1u);
        if ((o1 & 7u) == 7u) {
            unsigned o2 = atomicAdd(&g_l2, 1u);
            if ((o2 & 15u) == 15u) {
                __threadfence();
#pragma unroll
                for (int g = 0; g < 16; g++) g_gen[g * 32] = target;
            }
        }
        while (g_gen[(bx >> 3) * 32] < target) { }
        __threadfence();
    }
    __syncthreads();
}

// h0 [N][H] fp32 -> fp16 (same layout)
__global__ void h0_to_half(const float* __restrict__ in, __half* __restrict__ out) {
    int i = blockIdx.x * 256 + threadIdx.x;
    out[i] = __float2half_rn(in[i]);
}

// ---------------- fp32 GEMM (proven): C = act(A * W^T + bias) ----------------
// AMAP : A rows gathered from data [N][T][I]
// AHALF: A is fp16, plain row-major
// CMAP : C rows written to [N][T][O]
template<int AMAP, int AHALF, int CMAP, int RET>
__global__ void __launch_bounds__(256, 2) gemm128(
    const float* __restrict__ A, const float* __restrict__ W,
    const float* __restrict__ bias, float* __restrict__ C,
    int M, int Nc, int K)
{
    __shared__ float As[8][128];
    __shared__ float Bs[8][128];

    const int tid = threadIdx.x;
    const int m0 = blockIdx.x * 128;
    const int n0 = blockIdx.y * 128;

    const int warp = tid >> 5;
    const int lane = tid & 31;
    const int wm = warp & 3;
    const int wn = warp >> 2;
    const int tm = lane & 3;
    const int tn = lane >> 2;

    const int srow = tid >> 1;
    const int sk = (tid & 1) * 4;

    int r = m0 + srow;
    const float* Ap = 0;
    const __half* Ahp = 0;
    if (AMAP) {
        int nn = r & 63, tt = r >> 6;
        Ap = A + (size_t)(nn * Tt + tt) * K + sk;
    } else if (AHALF) {
        Ahp = (const __half*)A + (size_t)r * K + sk;
    } else {
        Ap = A + (size_t)r * K + sk;
    }
    const float* Wp = W + (size_t)(n0 + srow) * K + sk;

    ull acc[4][8];
#pragma unroll
    for (int i = 0; i < 4; i++)
#pragma unroll
        for (int j = 0; j < 8; j++) acc[i][j] = 0ull;

    float4 av = AHALF ? ld4h(Ahp) : *(const float4*)(Ap);
    float4 wv = *(const float4*)(Wp);

    const int aoff = wm * 32 + tm * 8;
    const int boff = wn * 64 + tn * 8;

    for (int k0 = 0; k0 < K; k0 += 8) {
        As[sk + 0][srow] = av.x;
        As[sk + 1][srow] = av.y;
        As[sk + 2][srow] = av.z;
        As[sk + 3][srow] = av.w;
        Bs[sk + 0][srow] = wv.x;
        Bs[sk + 1][srow] = wv.y;
        Bs[sk + 2][srow] = wv.z;
        Bs[sk + 3][srow] = wv.w;
        __syncthreads();
        if (k0 + 8 < K) {
            av = AHALF ? ld4h(Ahp + k0 + 8) : *(const float4*)(Ap + k0 + 8);
            wv = *(const float4*)(Wp + k0 + 8);
        }
#pragma unroll
        for (int kk = 0; kk < 8; kk++) {
            ulonglong2 a01 = *(const ulonglong2*)&As[kk][aoff];
            ulonglong2 a23 = *(const ulonglong2*)&As[kk][aoff + 4];
            float4 b0 = *(const float4*)&Bs[kk][boff];
            float4 b1 = *(const float4*)&Bs[kk][boff + 4];
            ull avv[4] = { a01.x, a01.y, a23.x, a23.y };
            ull bd[8];
            bd[0] = dup2(b0.x); bd[1] = dup2(b0.y);
            bd[2] = dup2(b0.z); bd[3] = dup2(b0.w);
            bd[4] = dup2(b1.x); bd[5] = dup2(b1.y);
            bd[6] = dup2(b1.z); bd[7] = dup2(b1.w);
#pragma unroll
            for (int i = 0; i < 4; i++)
#pragma unroll
                for (int j = 0; j < 8; j++)
                    acc[i][j] = ffma2(avv[i], bd[j], acc[i][j]);
        }
        __syncthreads();
    }

    float bb[8];
#pragma unroll
    for (int j = 0; j < 8; j++) bb[j] = bias[n0 + boff + j];

#pragma unroll
    for (int i = 0; i < 4; i++) {
        float o0[8], o1[8];
#pragma unroll
        for (int j = 0; j < 8; j++) {
            float2 u = unpack2(acc[i][j]);
            float x0 = u.x + bb[j], x1 = u.y + bb[j];
            if (RET) { x0 = retanh(x0); x1 = retanh(x1); }
            o0[j] = x0; o1[j] = x1;
        }
        int r0 = m0 + aoff + 2 * i;
        int r1 = r0 + 1;
        int cr0 = r0, cr1 = r1;
        if (CMAP) {
            cr0 = (r0 & 63) * Tt + (r0 >> 6);
            cr1 = (r1 & 63) * Tt + (r1 >> 6);
        }
        float4* p0 = (float4*)(C + (size_t)cr0 * Nc + n0 + boff);
        p0[0] = make_float4(o0[0], o0[1], o0[2], o0[3]);
        p0[1] = make_float4(o0[4], o0[5], o0[6], o0[7]);
        float4* p1 = (float4*)(C + (size_t)cr1 * Nc + n0 + boff);
        p1[0] = make_float4(o1[0], o1[1], o1[2], o1[3]);
        p1[1] = make_float4(o1[4], o1[5], o1[6], o1[7]);
    }
}

// ---------------- HMMA persistent RNN ----------------
// 128 CTAs x 256 thr. CTA gh computes h cols gh*8..+7 for all 64 n, K=1024.
// h state fp16 [T][N][H] (n-major). W split W_hi+W_lo fp16 in smem (error 2^-22).
// 8 warps = 4 m-tiles(16n) x 2 k-halves(512); fp32 accum; 2-way k-reduce in smem.
// A tile rows padded to 2064B -> conflict-free LDSM.
#define AS_STRIDE 1032                           // halfs per padded row
#define A_TILE_BYTES (64 * AS_STRIDE * 2)        // 132096
#define W_TILE_BYTES (16 * AS_STRIDE * 2)        // 33024
#define RNN_SMEM_BYTES (A_TILE_BYTES + W_TILE_BYTES + 2048)  // 167168

__global__ void __launch_bounds__(256, 1) rnn_mma(
    const __half* __restrict__ h016, const float* __restrict__ Wh,
    const float* __restrict__ bh, const float* __restrict__ inp,
    __half* __restrict__ hs16)
{
    extern __shared__ char smc[];
    __half* Asm = (__half*)smc;
    __half* Wsm = (__half*)(smc + A_TILE_BYTES);
    float* part = (float*)(smc + A_TILE_BYTES + W_TILE_BYTES);

    const int tid = threadIdx.x;
    const int bx = blockIdx.x;
    const int gh = bx;
    const int warp = tid >> 5;
    const int lane = tid & 31;
    const int wm = warp & 3;            // m-tile (16 n rows)
    const int wk = warp >> 2;           // k-half

    // stage W split once: row h = W_hi, row h+8 = W_lo
    for (int idx = tid; idx < 8192; idx += 256) {
        int h = idx >> 10;
        int k = idx & 1023;
        float w = Wh[(size_t)(gh * 8 + h) * Hh + k];
        __half whi = __float2half_rn(w);
        float lo = w - __half2float(whi);
        Wsm[h * AS_STRIDE + k] = whi;
        Wsm[(h + 8) * AS_STRIDE + k] = __float2half_rn(lo);
    }
    __syncthreads();

    // fragment mappings
    const int gr = lane >> 2;
    const int tc = lane & 3;
    const int hcol = gh * 8 + 2 * tc;
    const float2 bias2 = *(const float2*)(bh + hcol);

    const int arow = wm * 16 + (lane & 15);
    const unsigned abase = smem_u32(Asm + arow * AS_STRIDE) + ((lane >> 4) * 8) * 2;
    const int brow = lane & 7;
    const int bsel = ((lane & 15) >> 3) * 8;
    const unsigned bhib = smem_u32(Wsm + brow * AS_STRIDE + bsel);
    const unsigned blob = smem_u32(Wsm + (brow + 8) * AS_STRIDE + bsel);

    unsigned gen = 0;

    for (int t = 0; t < Tt; ++t) {
        const char* src = (const char*)(t ? (hs16 + (size_t)(t - 1) * NH) : h016);

        // stage full h[t-1] (128KB) into padded smem
#pragma unroll
        for (int j = 0; j < 32; j++) {
            int idx = j * 256 + tid;
            CP_ASYNC16(smem_u32((char*)Asm + (idx >> 7) * 2064 + (idx & 127) * 16),
                       src + (size_t)idx * 16);
        }
        CP_COMMIT();
        CP_WAIT0();
        __syncthreads();

        float c0 = 0.f, c1 = 0.f, c2 = 0.f, c3 = 0.f;
#pragma unroll
        for (int ks = 0; ks < 32; ks++) {
            int kb = wk * 512 + ks * 16;
            unsigned a0, a1, a2, a3, b0, b1;
            LDSM_X4(a0, a1, a2, a3, abase + kb * 2);
            LDSM_X2(b0, b1, bhib + kb * 2);
            MMA16816(c0, c1, c2, c3, a0, a1, a2, a3, b0, b1);
            LDSM_X2(b0, b1, blob + kb * 2);
            MMA16816(c0, c1, c2, c3, a0, a1, a2, a3, b0, b1);
        }

        // 2-way k reduce
        if (wk == 1) {
            float* p = part + wm * 128 + lane * 4;
            p[0] = c0; p[1] = c1; p[2] = c2; p[3] = c3;
        }
        __syncthreads();
        if (wk == 0) {
            const float* p = part + wm * 128 + lane * 4;
            c0 += p[0]; c1 += p[1]; c2 += p[2]; c3 += p[3];
            int na = wm * 16 + gr;
            int nb2 = na + 8;
            float2 ipa = *(const float2*)(inp + (size_t)t * NH + (size_t)na * Hh + hcol);
            float2 ipb = *(const float2*)(inp + (size_t)t * NH + (size_t)nb2 * Hh + hcol);
            float r0 = retanh(c0 + ipa.x + bias2.x);
            float r1 = retanh(c1 + ipa.y + bias2.y);
            float r2 = retanh(c2 + ipb.x + bias2.x);
            float r3 = retanh(c3 + ipb.y + bias2.y);
            __half2 ha = __floats2half2_rn(r0, r1);
            __half2 hb = __floats2half2_rn(r2, r3);
            *(__half2*)(hs16 + (size_t)t * NH + (size_t)na * Hh + hcol) = ha;
            *(__half2*)(hs16 + (size_t)t * NH + (size_t)nb2 * Hh + hcol) = hb;
        }

        tree_barrier(bx, ++gen);
    }
}

// ---------------- host ----------------
extern "C" void kernel_launch(void* const* d_in, const int* in_sizes, int n_in,
                              void* d_out, int out_size)
{
    const float* data = (const float*)d_in[0];
    const float* h0v  = (const float*)d_in[1];
    const float* h0m  = (const float*)d_in[2];
    const float* Wi   = (const float*)d_in[3];
    const float* bi   = (const float*)d_in[4];
    const float* Wh   = (const float*)d_in[5];
    const float* bh   = (const float*)d_in[6];
    const float* Wo   = (const float*)d_in[7];
    const float* bo   = (const float*)d_in[8];
    const float* Wt   = (const float*)d_in[9];
    const float* bt   = (const float*)d_in[10];
    const float* Wi2  = (const float*)d_in[11];
    const float* bi2  = (const float*)d_in[12];
    const float* Wh2  = (const float*)d_in[13];
    const float* bh2  = (const float*)d_in[14];
    const float* Wo2  = (const float*)d_in[15];
    const float* bo2  = (const float*)d_in[16];
    float* out = (float*)d_out;

    float *inp1, *inp2, *tmp, *outt;
    __half *hs16, *h016a, *h016b;
    cudaGetSymbolAddress((void**)&inp1,  g_inp1);
    cudaGetSymbolAddress((void**)&inp2,  g_inp2);
    cudaGetSymbolAddress((void**)&hs16,  g_hs16);
    cudaGetSymbolAddress((void**)&tmp,   g_tmp);
    cudaGetSymbolAddress((void**)&outt,  g_out_t);
    cudaGetSymbolAddress((void**)&h016a, g_h016a);
    cudaGetSymbolAddress((void**)&h016b, g_h016b);

    cudaFuncSetAttribute(rnn_mma,
                         cudaFuncAttributeMaxDynamicSharedMemorySize, RNN_SMEM_BYTES);

    dim3 blk(256);

    h0_to_half<<<256, blk>>>(h0v, h016a);                                          // 0
    h0_to_half<<<256, blk>>>(h0m, h016b);                                          // 1
    gemm128<1, 0, 0, 0><<<dim3(MROWS / 128, Hh / 128), blk>>>(data, Wi, bi, inp1, MROWS, Hh, Ii); // 2
    reset_barrier_kernel<<<1, 512>>>();                                            // 3
    reset_barrier_kernel<<<1, 512>>>();                                            // 4 (ncu pad)
    rnn_mma<<<RNN_NCTA, blk, RNN_SMEM_BYTES>>>(h016a, Wh, bh, inp1, hs16);         // 5 <- profiled

    gemm128<0, 1, 0, 0><<<dim3(MROWS / 128, Oo / 128), blk>>>((const float*)hs16, Wo, bo, tmp, MROWS, Oo, Hh);
    gemm128<0, 0, 0, 1><<<dim3(MROWS / 128, Oo / 128), blk>>>(tmp, Wt, bt, outt, MROWS, Oo, Oo);
    gemm128<0, 0, 0, 0><<<dim3(MROWS / 128, Hh / 128), blk>>>(outt, Wi2, bi2, inp2, MROWS, Hh, Oo);
    reset_barrier_kernel<<<1, 512>>>();
    rnn_mma<<<RNN_NCTA, blk, RNN_SMEM_BYTES>>>(h016b, Wh2, bh2, inp2, hs16);
    gemm128<0, 1, 1, 0><<<dim3(MROWS / 128, Oo / 128), blk>>>((const float*)hs16, Wo2, bo2, out, MROWS, Oo, Hh);
}

// round 16
// speedup vs baseline: 1.0595x; 1.0595x over previous
#include <cuda_runtime.h>
#include <cuda_fp16.h>
#include <math.h>

// Problem dims
#define Nb 64
#define Tt 512
#define Ii 512
#define Hh 1024
#define Oo 512
#define MROWS (Nb*Tt)
#define NH (Nb*Hh)
#define RNN_NCTA 128

typedef unsigned long long ull;

// ---------------- scratch ----------------
__device__ float  g_inp1 [(size_t)Tt * NH];      // inp_v [T][N][H] fp32
__device__ float  g_inp2 [(size_t)Tt * NH];      // inp_m [T][N][H] fp32
__device__ __half g_hs16 [(size_t)Tt * NH];      // h state fp16 [T][N][H]
__device__ float  g_tmp  [(size_t)Tt * Nb * Oo];
__device__ float  g_out_t[(size_t)Tt * Nb * Oo];
__device__ __half g_h016a[NH];
__device__ __half g_h016b[NH];
__device__ unsigned g_l1[16 * 32];
__device__ unsigned g_l2;
__device__ volatile unsigned g_gen[16 * 32];

// ---------------- helpers ----------------
__device__ __forceinline__ ull ffma2(ull a, ull b, ull c) {
    ull d;
    asm("fma.rn.f32x2 %0, %1, %2, %3;" : "=l"(d) : "l"(a), "l"(b), "l"(c));
    return d;
}
__device__ __forceinline__ float2 unpack2(ull v) {
    float2 r;
    asm("mov.b64 {%0, %1}, %2;" : "=f"(r.x), "=f"(r.y) : "l"(v));
    return r;
}
__device__ __forceinline__ ull dup2(float v) {
    ull r;
    asm("mov.b64 %0, {%1, %1};" : "=l"(r) : "f"(v));
    return r;
}
__device__ __forceinline__ float retanh(float x) {
    return x > 0.f ? tanhf(x) : 0.f;
}
__device__ __forceinline__ unsigned smem_u32(const void* p) {
    return (unsigned)__cvta_generic_to_shared(p);
}
__device__ __forceinline__ float4 ld4h(const __half* p) {
    uint2 u = *(const uint2*)p;
    __half2 a = *reinterpret_cast<__half2*>(&u.x);
    __half2 b = *reinterpret_cast<__half2*>(&u.y);
    float2 fa = __half22float2(a), fb = __half22float2(b);
    return make_float4(fa.x, fa.y, fb.x, fb.y);
}
#define CP_ASYNC16(dst, src) \
    asm volatile("cp.async.cg.shared.global [%0], [%1], 16;" :: "r"(dst), "l"(src))
#define CP_COMMIT() asm volatile("cp.async.commit_group;" ::: "memory")
__device__ __forceinline__ void cp_wait_n(int n) {
    if (n == 0) asm volatile("cp.async.wait_group 0;" ::: "memory");
    else        asm volatile("cp.async.wait_group 1;" ::: "memory");
}
#define LDSM_X4(r0, r1, r2, r3, addr) \
    asm volatile("ldmatrix.sync.aligned.m8n8.x4.shared.b16 {%0,%1,%2,%3}, [%4];" \
        : "=r"(r0), "=r"(r1), "=r"(r2), "=r"(r3) : "r"(addr))
#define LDSM_X2(r0, r1, addr) \
    asm volatile("ldmatrix.sync.aligned.m8n8.x2.shared.b16 {%0,%1}, [%2];" \
        : "=r"(r0), "=r"(r1) : "r"(addr))
#define MMA16816(c0, c1, c2, c3, a0, a1, a2, a3, b0, b1) \
    asm volatile("mma.sync.aligned.m16n8k16.row.col.f32.f16.f16.f32 " \
        "{%0,%1,%2,%3}, {%4,%5,%6,%7}, {%8,%9}, {%0,%1,%2,%3};" \
        : "+f"(c0), "+f"(c1), "+f"(c2), "+f"(c3) \
        : "r"(a0), "r"(a1), "r"(a2), "r"(a3), "r"(b0), "r"(b1))

__global__ void reset_barrier_kernel() {
    int t = threadIdx.x;
    if (t < 16 * 32) { g_l1[t] = 0u; g_gen[t] = 0u; }
    if (t == 0) g_l2 = 0u;
}

// tree arrival + fan-out release (16 gen lines, 8 pollers each)
__device__ __forceinline__ void tree_barrier(int bx, unsigned target) {
    __syncthreads();
    if (threadIdx.x == 0) {
        __threadfence();
        unsigned o1 = atomicAdd(&g_l1[(bx >> 3) * 32], 1u);
        if ((o1 & 7u) == 7u) {
            unsigned o2 = atomicAdd(&g_l2, 1u);
            if ((o2 & 15u) == 15u) {
                __threadfence();
#pragma unroll
                for (int g = 0; g < 16; g++) g_gen[g * 32] = target;
            }
        }
        while (g_gen[(bx >> 3) * 32] < target) { }
        __threadfence();
    }
    __syncthreads();
}

// h0 [N][H] fp32 -> fp16 (same layout)
__global__ void h0_to_half(const float* __restrict__ in, __half* __restrict__ out) {
    int i = blockIdx.x * 256 + threadIdx.x;
    out[i] = __float2half_rn(in[i]);
}

// ---------------- fp32 GEMM (proven): C = act(A * W^T + bias) ----------------
// AMAP : A rows gathered from data [N][T][I]
// AHALF: A is fp16, plain row-major
// CMAP : C rows written to [N][T][O]
template<int AMAP, int AHALF, int CMAP, int RET>
__global__ void __launch_bounds__(256, 2) gemm128(
    const float* __restrict__ A, const float* __restrict__ W,
    const float* __restrict__ bias, float* __restrict__ C,
    int M, int Nc, int K)
{
    __shared__ float As[8][128];
    __shared__ float Bs[8][128];

    const int tid = threadIdx.x;
    const int m0 = blockIdx.x * 128;
    const int n0 = blockIdx.y * 128;

    const int warp = tid >> 5;
    const int lane = tid & 31;
    const int wm = warp & 3;
    const int wn = warp >> 2;
    const int tm = lane & 3;
    const int tn = lane >> 2;

    const int srow = tid >> 1;
    const int sk = (tid & 1) * 4;

    int r = m0 + srow;
    const float* Ap = 0;
    const __half* Ahp = 0;
    if (AMAP) {
        int nn = r & 63, tt = r >> 6;
        Ap = A + (size_t)(nn * Tt + tt) * K + sk;
    } else if (AHALF) {
        Ahp = (const __half*)A + (size_t)r * K + sk;
    } else {
        Ap = A + (size_t)r * K + sk;
    }
    const float* Wp = W + (size_t)(n0 + srow) * K + sk;

    ull acc[4][8];
#pragma unroll
    for (int i = 0; i < 4; i++)
#pragma unroll
        for (int j = 0; j < 8; j++) acc[i][j] = 0ull;

    float4 av = AHALF ? ld4h(Ahp) : *(const float4*)(Ap);
    float4 wv = *(const float4*)(Wp);

    const int aoff = wm * 32 + tm * 8;
    const int boff = wn * 64 + tn * 8;

    for (int k0 = 0; k0 < K; k0 += 8) {
        As[sk + 0][srow] = av.x;
        As[sk + 1][srow] = av.y;
        As[sk + 2][srow] = av.z;
        As[sk + 3][srow] = av.w;
        Bs[sk + 0][srow] = wv.x;
        Bs[sk + 1][srow] = wv.y;
        Bs[sk + 2][srow] = wv.z;
        Bs[sk + 3][srow] = wv.w;
        __syncthreads();
        if (k0 + 8 < K) {
            av = AHALF ? ld4h(Ahp + k0 + 8) : *(const float4*)(Ap + k0 + 8);
            wv = *(const float4*)(Wp + k0 + 8);
        }
#pragma unroll
        for (int kk = 0; kk < 8; kk++) {
            ulonglong2 a01 = *(const ulonglong2*)&As[kk][aoff];
            ulonglong2 a23 = *(const ulonglong2*)&As[kk][aoff + 4];
            float4 b0 = *(const float4*)&Bs[kk][boff];
            float4 b1 = *(const float4*)&Bs[kk][boff + 4];
            ull avv[4] = { a01.x, a01.y, a23.x, a23.y };
            ull bd[8];
            bd[0] = dup2(b0.x); bd[1] = dup2(b0.y);
            bd[2] = dup2(b0.z); bd[3] = dup2(b0.w);
            bd[4] = dup2(b1.x); bd[5] = dup2(b1.y);
            bd[6] = dup2(b1.z); bd[7] = dup2(b1.w);
#pragma unroll
            for (int i = 0; i < 4; i++)
#pragma unroll
                for (int j = 0; j < 8; j++)
                    acc[i][j] = ffma2(avv[i], bd[j], acc[i][j]);
        }
        __syncthreads();
    }

    float bb[8];
#pragma unroll
    for (int j = 0; j < 8; j++) bb[j] = bias[n0 + boff + j];

#pragma unroll
    for (int i = 0; i < 4; i++) {
        float o0[8], o1[8];
#pragma unroll
        for (int j = 0; j < 8; j++) {
            float2 u = unpack2(acc[i][j]);
            float x0 = u.x + bb[j], x1 = u.y + bb[j];
            if (RET) { x0 = retanh(x0); x1 = retanh(x1); }
            o0[j] = x0; o1[j] = x1;
        }
        int r0 = m0 + aoff + 2 * i;
        int r1 = r0 + 1;
        int cr0 = r0, cr1 = r1;
        if (CMAP) {
            cr0 = (r0 & 63) * Tt + (r0 >> 6);
            cr1 = (r1 & 63) * Tt + (r1 >> 6);
        }
        float4* p0 = (float4*)(C + (size_t)cr0 * Nc + n0 + boff);
        p0[0] = make_float4(o0[0], o0[1], o0[2], o0[3]);
        p0[1] = make_float4(o0[4], o0[5], o0[6], o0[7]);
        float4* p1 = (float4*)(C + (size_t)cr1 * Nc + n0 + boff);
        p1[0] = make_float4(o1[0], o1[1], o1[2], o1[3]);
        p1[1] = make_float4(o1[4], o1[5], o1[6], o1[7]);
    }
}

// ---------------- HMMA persistent RNN (pipelined staging) ----------------
// 128 CTAs x 256 thr. CTA gh computes h cols gh*8..+7 for all 64 n, K=1024.
// h state fp16 [T][N][H]. W split W_hi+W_lo fp16 in smem (validated 3.4e-4).
// A tile [64 n][1024 k] fp16, rows padded to 2064B. Staging split into 4
// k-chunks of 32KB (disjoint smem columns) -> cp.async depth-2 overlap.
// 8 warps = 4 m-tiles(16n) x 2 k-halves; fp32 accum; 2-way k-reduce in smem.
#define AS_STRIDE 1032                           // halfs per padded row
#define A_TILE_BYTES (64 * AS_STRIDE * 2)        // 132096
#define W_TILE_BYTES (16 * AS_STRIDE * 2)        // 33024
#define RNN_SMEM_BYTES (A_TILE_BYTES + W_TILE_BYTES + 2048)  // 167168

__global__ void __launch_bounds__(256, 1) rnn_mma(
    const __half* __restrict__ h016, const float* __restrict__ Wh,
    const float* __restrict__ bh, const float* __restrict__ inp,
    __half* __restrict__ hs16)
{
    extern __shared__ char smc[];
    __half* Asm = (__half*)smc;
    __half* Wsm = (__half*)(smc + A_TILE_BYTES);
    float* part = (float*)(smc + A_TILE_BYTES + W_TILE_BYTES);

    const int tid = threadIdx.x;
    const int bx = blockIdx.x;
    const int gh = bx;
    const int warp = tid >> 5;
    const int lane = tid & 31;
    const int wm = warp & 3;            // m-tile (16 n rows)
    const int wk = warp >> 2;           // k-half

    // stage W split once: row h = W_hi, row h+8 = W_lo
    for (int idx = tid; idx < 8192; idx += 256) {
        int h = idx >> 10;
        int k = idx & 1023;
        float w = Wh[(size_t)(gh * 8 + h) * Hh + k];
        __half whi = __float2half_rn(w);
        float lo = w - __half2float(whi);
        Wsm[h * AS_STRIDE + k] = whi;
        Wsm[(h + 8) * AS_STRIDE + k] = __float2half_rn(lo);
    }
    __syncthreads();

    // fragment mappings (identical to validated R14)
    const int gr = lane >> 2;
    const int tc = lane & 3;
    const int hcol = gh * 8 + 2 * tc;
    const float2 bias2 = *(const float2*)(bh + hcol);

    const int arow = wm * 16 + (lane & 15);
    const unsigned abase = smem_u32(Asm + arow * AS_STRIDE) + ((lane >> 4) * 8) * 2;
    const int brow = lane & 7;
    const int bsel = ((lane & 15) >> 3) * 8;
    const unsigned bhib = smem_u32(Wsm + brow * AS_STRIDE + bsel);
    const unsigned blob = smem_u32(Wsm + (brow + 8) * AS_STRIDE + bsel);

    // staging piece offsets (8 x 16B per thread per 32KB chunk)
    // chunk c = k columns [c*256, (c+1)*256) of all 64 rows
    unsigned gen = 0;

    for (int t = 0; t < Tt; ++t) {
        const char* src = (const char*)(t ? (hs16 + (size_t)(t - 1) * NH) : h016);

        // prologue: stage chunks 0, 1
#pragma unroll
        for (int pc = 0; pc < 2; pc++) {
#pragma unroll
            for (int j = 0; j < 8; j++) {
                int idx = j * 256 + tid;          // 0..2047
                int row = idx >> 5;
                int piece = idx & 31;
                CP_ASYNC16(smem_u32((char*)Asm + row * 2064 + pc * 512 + piece * 16),
                           src + (size_t)row * 2048 + pc * 512 + piece * 16);
            }
            CP_COMMIT();
        }

        float c0 = 0.f, c1 = 0.f, c2 = 0.f, c3 = 0.f;

#pragma unroll
        for (int c = 0; c < 4; c++) {
            cp_wait_n(c < 3 ? 1 : 0);
            __syncthreads();
            if (c + 2 < 4) {
                int pc = c + 2;
#pragma unroll
                for (int j = 0; j < 8; j++) {
                    int idx = j * 256 + tid;
                    int row = idx >> 5;
                    int piece = idx & 31;
                    CP_ASYNC16(smem_u32((char*)Asm + row * 2064 + pc * 512 + piece * 16),
                               src + (size_t)row * 2048 + pc * 512 + piece * 16);
                }
                CP_COMMIT();
            }
            // compute chunk c: k in [c*256 + wk*128, +128), 8 MMA k-steps
#pragma unroll
            for (int ks = 0; ks < 8; ks++) {
                int kb = c * 256 + wk * 128 + ks * 16;
                unsigned a0, a1, a2, a3, b0, b1;
                LDSM_X4(a0, a1, a2, a3, abase + kb * 2);
                LDSM_X2(b0, b1, bhib + kb * 2);
                MMA16816(c0, c1, c2, c3, a0, a1, a2, a3, b0, b1);
                LDSM_X2(b0, b1, blob + kb * 2);
                MMA16816(c0, c1, c2, c3, a0, a1, a2, a3, b0, b1);
            }
        }

        // 2-way k reduce
        if (wk == 1) {
            float* p = part + wm * 128 + lane * 4;
            p[0] = c0; p[1] = c1; p[2] = c2; p[3] = c3;
        }
        __syncthreads();
        if (wk == 0) {
            const float* p = part + wm * 128 + lane * 4;
            c0 += p[0]; c1 += p[1]; c2 += p[2]; c3 += p[3];
            int na = wm * 16 + gr;
            int nb2 = na + 8;
            float2 ipa = *(const float2*)(inp + (size_t)t * NH + (size_t)na * Hh + hcol);
            float2 ipb = *(const float2*)(inp + (size_t)t * NH + (size_t)nb2 * Hh + hcol);
            float r0 = retanh(c0 + ipa.x + bias2.x);
            float r1 = retanh(c1 + ipa.y + bias2.y);
            float r2 = retanh(c2 + ipb.x + bias2.x);
            float r3 = retanh(c3 + ipb.y + bias2.y);
            __half2 ha = __floats2half2_rn(r0, r1);
            __half2 hb = __floats2half2_rn(r2, r3);
            *(__half2*)(hs16 + (size_t)t * NH + (size_t)na * Hh + hcol) = ha;
            *(__half2*)(hs16 + (size_t)t * NH + (size_t)nb2 * Hh + hcol) = hb;
        }

        tree_barrier(bx, ++gen);
    }
}

// ---------------- host ----------------
extern "C" void kernel_launch(void* const* d_in, const int* in_sizes, int n_in,
                              void* d_out, int out_size)
{
    const float* data = (const float*)d_in[0];
    const float* h0v  = (const float*)d_in[1];
    const float* h0m  = (const float*)d_in[2];
    const float* Wi   = (const float*)d_in[3];
    const float* bi   = (const float*)d_in[4];
    const float* Wh   = (const float*)d_in[5];
    const float* bh   = (const float*)d_in[6];
    const float* Wo   = (const float*)d_in[7];
    const float* bo   = (const float*)d_in[8];
    const float* Wt   = (const float*)d_in[9];
    const float* bt   = (const float*)d_in[10];
    const float* Wi2  = (const float*)d_in[11];
    const float* bi2  = (const float*)d_in[12];
    const float* Wh2  = (const float*)d_in[13];
    const float* bh2  = (const float*)d_in[14];
    const float* Wo2  = (const float*)d_in[15];
    const float* bo2  = (const float*)d_in[16];
    float* out = (float*)d_out;

    float *inp1, *inp2, *tmp, *outt;
    __half *hs16, *h016a, *h016b;
    cudaGetSymbolAddress((void**)&inp1,  g_inp1);
    cudaGetSymbolAddress((void**)&inp2,  g_inp2);
    cudaGetSymbolAddress((void**)&hs16,  g_hs16);
    cudaGetSymbolAddress((void**)&tmp,   g_tmp);
    cudaGetSymbolAddress((void**)&outt,  g_out_t);
    cudaGetSymbolAddress((void**)&h016a, g_h016a);
    cudaGetSymbolAddress((void**)&h016b, g_h016b);

    cudaFuncSetAttribute(rnn_mma,
                         cudaFuncAttributeMaxDynamicSharedMemorySize, RNN_SMEM_BYTES);

    dim3 blk(256);

    h0_to_half<<<256, blk>>>(h0v, h016a);                                          // 0
    h0_to_half<<<256, blk>>>(h0m, h016b);                                          // 1
    gemm128<1, 0, 0, 0><<<dim3(MROWS / 128, Hh / 128), blk>>>(data, Wi, bi, inp1, MROWS, Hh, Ii); // 2
    reset_barrier_kernel<<<1, 512>>>();                                            // 3
    reset_barrier_kernel<<<1, 512>>>();                                            // 4 (ncu pad)
    rnn_mma<<<RNN_NCTA, blk, RNN_SMEM_BYTES>>>(h016a, Wh, bh, inp1, hs16);         // 5 <- profiled

    gemm128<0, 1, 0, 0><<<dim3(MROWS / 128, Oo / 128), blk>>>((const float*)hs16, Wo, bo, tmp, MROWS, Oo, Hh);
    gemm128<0, 0, 0, 1><<<dim3(MROWS / 128, Oo / 128), blk>>>(tmp, Wt, bt, outt, MROWS, Oo, Oo);
    gemm128<0, 0, 0, 0><<<dim3(MROWS / 128, Hh / 128), blk>>>(outt, Wi2, bi2, inp2, MROWS, Hh, Oo);
    reset_barrier_kernel<<<1, 512>>>();
    rnn_mma<<<RNN_NCTA, blk, RNN_SMEM_BYTES>>>(h016b, Wh2, bh2, inp2, hs16);
    gemm128<0, 1, 1, 0><<<dim3(MROWS / 128, Oo / 128), blk>>>((const float*)hs16, Wo2, bo2, out, MROWS, Oo, Hh);
}